// round 16
// baseline (speedup 1.0000x reference)
#include <cuda_runtime.h>
#include <cuda_bf16.h>
#include <cstdint>

// Problem dims
#define VOCAB 8192
#define HID   1024
#define BATCH 64
#define SEQ   256

#define NBLK  128      // persistent blocks (1 per SM, <=148 -> co-resident)

typedef unsigned long long ull;

// -------- device scratch (static: no runtime allocation allowed) --------
__device__ __align__(16) float g_H[(size_t)SEQ * BATCH * HID];  // hidden states [t][b][j] (GEMM layout)
__device__ __align__(16) float g_h[2][HID * BATCH];             // ping-pong h TRANSPOSED: [k][b]
__device__ unsigned g_flag[SEQ * NBLK];  // producer flags: ((t+1)<<1)|epoch
__device__ unsigned g_epoch;             // flipped each launch (graph replay safety)

// transpose status (B,H) -> g_h[0] = hT (H,B); flip epoch
__global__ void k_init_t(const float* __restrict__ status) {
    __shared__ float tile[32][33];
    int j0 = blockIdx.x * 32, b0 = blockIdx.y * 32;
    int tx = threadIdx.x, ty = threadIdx.y;
    #pragma unroll
    for (int i = 0; i < 32; i += 8)
        tile[ty + i][tx] = status[(size_t)(b0 + ty + i) * HID + j0 + tx];   // coalesced over j
    __syncthreads();
    #pragma unroll
    for (int i = 0; i < 32; i += 8)
        g_h[0][(size_t)(j0 + ty + i) * BATCH + b0 + tx] = tile[tx][ty + i]; // coalesced over b
    if (blockIdx.x == 0 && blockIdx.y == 0 && tx == 0 && ty == 0) g_epoch ^= 1u;
}

// packed dual fp32 FMA (sm_100+): acc = a*b + acc elementwise on f32x2
__device__ __forceinline__ void ffma2(ull& acc, ull a, ull b) {
    asm("fma.rn.f32x2 %0, %1, %2, %0;" : "+l"(acc) : "l"(a), "l"(b));
}

// cp.async 16B, L2-only (.cg) — required: h is produced by other SMs each step
__device__ __forceinline__ void cp16(uint32_t saddr, const float* g) {
    asm volatile("cp.async.cg.shared.global [%0], [%1], 16;" :: "r"(saddr), "l"(g));
}
#define CP_COMMIT() asm volatile("cp.async.commit_group;" ::: "memory")
#define CP_WAIT(N)  asm volatile("cp.async.wait_group %0;" :: "n"(N) : "memory")

__device__ __forceinline__ unsigned ld_acq(const unsigned* p) {
    unsigned v;
    asm volatile("ld.acquire.gpu.global.u32 %0, [%1];" : "=r"(v) : "l"(p) : "memory");
    return v;
}

// ---------------------------------------------------------------
// Persistent RNN recurrence, all 256 steps, NO central barrier.
// Block (64 j-groups x 2 b-halves): owns 16-j slice of w_hh
// (dup-packed in smem, 128KB, staged once) and a 32-b slice.
// Warp w owns k in [w*128, +128): streams 8 pieces of 16k x 32b
// via cp.async.cg triple-buffer. Each piece p's data was produced
// last step by exactly one block (jblk=8w+p, same b-half) -> warp
// polls that block's flag right before issuing the piece.
// dyn smem: wdup 128KB + hbuf 48KB + red 16KB = 192KB (1 blk/SM).
// ---------------------------------------------------------------
__global__ __launch_bounds__(256, 1) void k_rnn(
    const int* __restrict__ X, const float* __restrict__ w_xh,
    const float* __restrict__ w_hh, const float* __restrict__ b_h)
{
    extern __shared__ float smem[];
    float* wdup = smem;                         // [1024][32]: (w[k][j],w[k][j]) pairs, 16 j
    float* hbuf = smem + 32768;                 // [8 warps][3 bufs][16k][32b]
    ull*   red  = (ull*)(smem + 32768 + 12288); // [8][256] f32x2 partials

    const int tid  = threadIdx.x;
    const int warp = tid >> 5;
    const int lane = tid & 31;
    const int bpg  = lane & 3;                  // 4 b-pair groups (4 bp each)
    const int jq   = lane >> 2;                 // 8 j-quads (2 j each)
    const int jbase = (blockIdx.x >> 1) * 16;
    const int bhalf = blockIdx.x & 1;
    const int bbase = bhalf * 32;
    const int ks    = warp * 128;               // warp's k-slice start
    const unsigned epoch = g_epoch;

    // ---- stage w slice once, duplicated pairs [k][(j0,j0,j1,j1,...)] ----
    for (int k = tid; k < HID; k += 256) {
        const float* wr = w_hh + (size_t)k * HID + jbase;
        float* d = wdup + k * 32;
        #pragma unroll
        for (int j = 0; j < 16; j++) {
            float v = wr[j];
            *(float2*)&d[2 * j] = make_float2(v, v);
        }
    }

    float* mybuf = hbuf + warp * (3 * 512);
    uint32_t sb0 = (uint32_t)__cvta_generic_to_shared(mybuf);
    const uint32_t sbv[3] = {sb0, sb0 + 512u * 4u, sb0 + 1024u * 4u};

    // epilogue constants: thread -> (j = ej, b-pair ebp)
    const int ej  = tid >> 4;                   // 0..15
    const int ebp = tid & 15;                   // 0..15
    const int eb  = bbase + 2 * ebp;
    const float bh = b_h[jbase + ej];

    __syncthreads();

    #pragma unroll 1
    for (int t = 0; t < SEQ; t++) {
        const float* __restrict__ hin  = g_h[t & 1];        // hT [k][64]
        float* __restrict__ hout = g_h[(t & 1) ^ 1];

        // ---- hoisted embedding gather (depends only on t; hides under compute) ----
        int xi0 = __ldg(&X[eb * SEQ + t]);
        int xi1 = __ldg(&X[(eb + 1) * SEQ + t]);
        float e0 = __ldg(&w_xh[(size_t)xi0 * HID + jbase + ej]);
        float e1 = __ldg(&w_xh[(size_t)xi1 * HID + jbase + ej]);

        // wait for the single producer of piece p (jblk = 8*warp+p, same b-half)
        #define WAITP(p) { \
            if (t > 0 && lane == 0) { \
                const unsigned expv = ((unsigned)t << 1) | epoch; \
                const unsigned* fa = &g_flag[(size_t)(t - 1) * NBLK + ((8 * warp + (p)) * 2 + bhalf)]; \
                unsigned v = ld_acq(fa); \
                while (v != expv) { __nanosleep(20); v = ld_acq(fa); } \
            } \
            __syncwarp(); }

        // issue piece p (16k x 32b, 2KB) into buffer bi_
        #define ISSUE(p, bi_) { \
            _Pragma("unroll") \
            for (int q = 0; q < 4; q++) { \
                int i = lane + q * 32; int kl = i >> 3; int bo = (i & 7) * 4; \
                cp16(sbv[bi_] + (uint32_t)(kl * 32 + bo) * 4u, \
                     hin + (size_t)(ks + (p) * 16 + kl) * BATCH + bbase + bo); \
            } \
            CP_COMMIT(); }

        ull acc[4][2];
        #pragma unroll
        for (int bi = 0; bi < 4; bi++) { acc[bi][0] = 0ull; acc[bi][1] = 0ull; }

        WAITP(0); ISSUE(0, 0);
        WAITP(1); ISSUE(1, 1);
        WAITP(2); ISSUE(2, 2);

        // compute piece c from buffer c%3 (data k = ks + c*16 ..)
        #define PIECE(c, NW) { \
            CP_WAIT(NW); __syncwarp(); \
            const float* hb = mybuf + ((c) % 3) * 512; \
            const float* wp = wdup + (size_t)(ks + (c) * 16) * 32; \
            _Pragma("unroll") \
            for (int kl = 0; kl < 16; kl++) { \
                ulonglong2 wv  = *(const ulonglong2*)(wp + kl * 32 + jq * 4); \
                ulonglong2 h01 = *(const ulonglong2*)(hb + kl * 32 + bpg * 8); \
                ulonglong2 h23 = *(const ulonglong2*)(hb + kl * 32 + bpg * 8 + 4); \
                ffma2(acc[0][0], h01.x, wv.x); ffma2(acc[0][1], h01.x, wv.y); \
                ffma2(acc[1][0], h01.y, wv.x); ffma2(acc[1][1], h01.y, wv.y); \
                ffma2(acc[2][0], h23.x, wv.x); ffma2(acc[2][1], h23.x, wv.y); \
                ffma2(acc[3][0], h23.y, wv.x); ffma2(acc[3][1], h23.y, wv.y); \
            } \
            __syncwarp(); }

        PIECE(0, 2); WAITP(3); ISSUE(3, 0);
        PIECE(1, 2); WAITP(4); ISSUE(4, 1);
        PIECE(2, 2); WAITP(5); ISSUE(5, 2);
        PIECE(3, 2); WAITP(6); ISSUE(6, 0);
        PIECE(4, 2); WAITP(7); ISSUE(7, 1);
        PIECE(5, 2);
        PIECE(6, 1);
        PIECE(7, 0);

        // ---- split-k partial dump: o = j*16 + bp (f32x2 over b-pair) ----
        #pragma unroll
        for (int jj = 0; jj < 2; jj++) {
            int o2 = (jq * 2 + jj) * 16 + bpg * 4;
            ulonglong2 v01; v01.x = acc[0][jj]; v01.y = acc[1][jj];
            ulonglong2 v23; v23.x = acc[2][jj]; v23.y = acc[3][jj];
            *(ulonglong2*)&red[warp * 256 + o2]     = v01;
            *(ulonglong2*)&red[warp * 256 + o2 + 2] = v23;
        }
        __syncthreads();

        // ---- final reduce + epilogue ----
        float2 s = make_float2(0.f, 0.f);
        #pragma unroll
        for (int w = 0; w < 8; w++) {
            float2 v = *(const float2*)&red[w * 256 + tid];
            s.x += v.x; s.y += v.y;
        }
        float v0 = tanhf(s.x + e0 + bh);
        float v1 = tanhf(s.y + e1 + bh);
        __stcg((float2*)&hout[(size_t)(jbase + ej) * BATCH + eb], make_float2(v0, v1));
        g_H[((size_t)t * BATCH + eb) * HID + jbase + ej]     = v0;
        g_H[((size_t)t * BATCH + eb + 1) * HID + jbase + ej] = v1;

        __syncthreads();   // all hout stores issued + red consumed before flag / next step

        // ---- publish: this block's 16 hT rows for step t are ready ----
        if (tid == 0) {
            __threadfence();
            unsigned fv = ((unsigned)(t + 1) << 1) | epoch;
            asm volatile("st.release.gpu.global.u32 [%0], %1;"
                         :: "l"(&g_flag[(size_t)t * NBLK + blockIdx.x]), "r"(fv) : "memory");
        }
        #undef WAITP
        #undef ISSUE
        #undef PIECE
    }
}

// ---------------------------------------------------------------
// Big output GEMM with tf32 mma.sync:
//   Y[m, n] = sum_k H[m,k] * w_ho[k,n] + b_o[n]
// M = 16384, K = 1024, N = 8192, fp32 accumulate.
// Block tile 128x128, BK=32, 8 warps (4x2), warp tile 32x64.
// tf32 conversion at smem-store; register-prefetch pipeline hides
// global load latency behind the MMA work of the previous tile.
// ---------------------------------------------------------------
__device__ __forceinline__ uint32_t f2tf32(float x) {
    uint32_t r;
    asm("cvt.rna.tf32.f32 %0, %1;" : "=r"(r) : "f"(x));
    return r;
}

__device__ __forceinline__ void mma_16n8k8(float* c, const uint32_t* a, const uint32_t* b) {
    asm volatile(
        "mma.sync.aligned.m16n8k8.row.col.f32.tf32.tf32.f32 "
        "{%0,%1,%2,%3}, {%4,%5,%6,%7}, {%8,%9}, {%0,%1,%2,%3};\n"
        : "+f"(c[0]), "+f"(c[1]), "+f"(c[2]), "+f"(c[3])
        : "r"(a[0]), "r"(a[1]), "r"(a[2]), "r"(a[3]), "r"(b[0]), "r"(b[1]));
}

__global__ __launch_bounds__(256) void k_gemm(
    const float* __restrict__ Wo, const float* __restrict__ b_o,
    float* __restrict__ Y)
{
    __shared__ uint32_t As[128][36];   // [m][k] tf32
    __shared__ uint32_t Bs[128][36];   // [n][k] tf32 (transposed tile of w_ho)

    const int m0 = blockIdx.y * 128;
    const int n0 = blockIdx.x * 128;
    const int tid = threadIdx.x;
    const int warp = tid >> 5, lane = tid & 31;
    const int wr = warp >> 1;       // 0..3  (m direction, 32 rows each)
    const int wc = warp & 1;        // 0..1  (n direction, 64 cols each)
    const int g = lane >> 2;        // groupID
    const int tg = lane & 3;        // thread in group

    // per-thread staging addresses (fixed across tiles)
    const int a_row = tid >> 3, a_c4 = (tid & 7) << 2;          // + r*32 rows
    const int b_k = tid >> 5, b_n4 = (tid & 31) << 2;           // + r*8 k

    float c[2][8][4];
    #pragma unroll
    for (int i = 0; i < 2; i++)
        #pragma unroll
        for (int jn = 0; jn < 8; jn++)
            #pragma unroll
            for (int q = 0; q < 4; q++) c[i][jn][q] = 0.f;

    float4 ra[4], rb[4];
    #define LDG_T(kt) { \
        _Pragma("unroll") \
        for (int r = 0; r < 4; r++) { \
            ra[r] = *reinterpret_cast<const float4*>( \
                &g_H[((size_t)(m0 + a_row + r * 32)) * HID + (kt) + a_c4]); \
            rb[r] = *reinterpret_cast<const float4*>( \
                &Wo[((size_t)((kt) + b_k + r * 8)) * VOCAB + n0 + b_n4]); \
        } }

    LDG_T(0);

    for (int kt = 0; kt < HID; kt += 32) {
        // STS current tile (cvt once here)
        #pragma unroll
        for (int r = 0; r < 4; r++) {
            int row = a_row + r * 32;
            As[row][a_c4 + 0] = f2tf32(ra[r].x); As[row][a_c4 + 1] = f2tf32(ra[r].y);
            As[row][a_c4 + 2] = f2tf32(ra[r].z); As[row][a_c4 + 3] = f2tf32(ra[r].w);
            int k = b_k + r * 8;
            Bs[b_n4 + 0][k] = f2tf32(rb[r].x); Bs[b_n4 + 1][k] = f2tf32(rb[r].y);
            Bs[b_n4 + 2][k] = f2tf32(rb[r].z); Bs[b_n4 + 3][k] = f2tf32(rb[r].w);
        }
        __syncthreads();

        if (kt + 32 < HID) LDG_T(kt + 32);   // prefetch next tile into registers

        #pragma unroll
        for (int kk = 0; kk < 4; kk++) {
            uint32_t a[2][4];
            #pragma unroll
            for (int im = 0; im < 2; im++) {
                int row = wr * 32 + im * 16;
                a[im][0] = As[row + g][kk * 8 + tg];
                a[im][1] = As[row + g + 8][kk * 8 + tg];
                a[im][2] = As[row + g][kk * 8 + tg + 4];
                a[im][3] = As[row + g + 8][kk * 8 + tg + 4];
            }
            uint32_t b[8][2];
            #pragma unroll
            for (int in = 0; in < 8; in++) {
                int n = wc * 64 + in * 8 + g;
                b[in][0] = Bs[n][kk * 8 + tg];
                b[in][1] = Bs[n][kk * 8 + tg + 4];
            }
            #pragma unroll
            for (int im = 0; im < 2; im++)
                #pragma unroll
                for (int in = 0; in < 8; in++)
                    mma_16n8k8(c[im][in], a[im], b[in]);
        }
        __syncthreads();
    }
    #undef LDG_T

    // epilogue: add bias, write fp32 Y
    #pragma unroll
    for (int im = 0; im < 2; im++) {
        #pragma unroll
        for (int in = 0; in < 8; in++) {
            int col = n0 + wc * 64 + in * 8 + tg * 2;
            float bo0 = b_o[col], bo1 = b_o[col + 1];
            int row0 = m0 + wr * 32 + im * 16 + g;
            float2 v0 = make_float2(c[im][in][0] + bo0, c[im][in][1] + bo1);
            float2 v1 = make_float2(c[im][in][2] + bo0, c[im][in][3] + bo1);
            *reinterpret_cast<float2*>(&Y[(size_t)row0 * VOCAB + col]) = v0;
            *reinterpret_cast<float2*>(&Y[((size_t)row0 + 8) * VOCAB + col]) = v1;
        }
    }
}

// de-transpose final hidden state: dst[b][j] = g_h[0][j][b]
__global__ void k_hfinal_t(float* __restrict__ dst) {
    __shared__ float tile[32][33];
    int j0 = blockIdx.x * 32, b0 = blockIdx.y * 32;
    int tx = threadIdx.x, ty = threadIdx.y;
    #pragma unroll
    for (int i = 0; i < 32; i += 8)
        tile[ty + i][tx] = g_h[0][(size_t)(j0 + ty + i) * BATCH + b0 + tx];  // coalesced over b
    __syncthreads();
    #pragma unroll
    for (int i = 0; i < 32; i += 8)
        dst[(size_t)(b0 + ty + i) * HID + j0 + tx] = tile[tx][ty + i];       // coalesced over j
}

// ---------------------------------------------------------------
extern "C" void kernel_launch(void* const* d_in, const int* in_sizes, int n_in,
                              void* d_out, int out_size) {
    const int*   X      = (const int*)d_in[0];    // (B, S) int32
    const float* status = (const float*)d_in[1];  // (B, H)
    const float* w_xh   = (const float*)d_in[2];  // (V, H)
    const float* w_hh   = (const float*)d_in[3];  // (H, H)
    const float* w_ho   = (const float*)d_in[4];  // (H, V)
    const float* b_h    = (const float*)d_in[5];  // (H)
    const float* b_o    = (const float*)d_in[6];  // (V)
    float* out = (float*)d_out;

    const int smem_bytes = (32768 + 12288 + 4096) * 4;   // 196,608 B (192 KB)
    cudaFuncSetAttribute(k_rnn, cudaFuncAttributeMaxDynamicSharedMemorySize, smem_bytes);

    k_init_t<<<dim3(HID / 32, BATCH / 32), dim3(32, 8)>>>(status);

    // all 256 recurrence steps in one persistent kernel (flag-synced)
    k_rnn<<<NBLK, 256, smem_bytes>>>(X, w_xh, w_hh, b_h);

    // Y: (S*B, V) = (16384, 8192)
    k_gemm<<<dim3(VOCAB / 128, (SEQ * BATCH) / 128), 256>>>(w_ho, b_o, out);

    // h_final appended after Y if the output buffer expects it
    long long ybytes = (long long)SEQ * BATCH * VOCAB;
    if ((long long)out_size >= ybytes + (long long)BATCH * HID)
        k_hfinal_t<<<dim3(HID / 32, BATCH / 32), dim3(32, 8)>>>(out + (size_t)SEQ * BATCH * VOCAB);
}